// round 15
// baseline (speedup 1.0000x reference)
#include <cuda_runtime.h>
#include <cuda_bf16.h>
#include <cstdint>

// ---------------- problem constants ----------------
#define BATCH   16
#define DMODEL  256
#define KCODES  512
#define HP      128
#define WP      128
#define NROWS   (BATCH*HP*WP)
#define QUANT_ELEMS ((long long)BATCH*DMODEL*HP*WP)   // 67108864
#define IDX_ELEMS   (BATCH*HP*WP)
#define BN_EPS 1e-5f
#define MARGIN 4.0f
#define NCTA 4096

// ---------------- scratch ----------------
__device__ __nv_bfloat16  g_cbkb[KCODES * DMODEL];
__device__ float g_c2[KCODES];
__device__ float g_conv_partial[NCTA];
__device__ float g_vq_partial[NCTA];
__device__ unsigned g_done;

// ---------------- helpers ----------------
__device__ __forceinline__ unsigned long long pack2(float a, float b) {
    unsigned long long r;
    asm("mov.b64 %0, {%1, %2};" : "=l"(r) : "f"(a), "f"(b));
    return r;
}
__device__ __forceinline__ void unpack2(unsigned long long v, float& a, float& b) {
    asm("mov.b64 {%0, %1}, %2;" : "=f"(a), "=f"(b) : "l"(v));
}
__device__ __forceinline__ void fma2(unsigned long long& acc,
                                     unsigned long long a, unsigned long long b) {
    asm("fma.rn.f32x2 %0, %1, %2, %3;" : "=l"(acc) : "l"(a), "l"(b), "l"(acc));
}
__device__ __forceinline__ unsigned fenc(float f) {
    unsigned u = __float_as_uint(f);
    return (u & 0x80000000u) ? ~u : (u | 0x80000000u);
}
__device__ __forceinline__ float fdec(unsigned e) {
    unsigned u = (e & 0x80000000u) ? (e ^ 0x80000000u) : ~e;
    return __uint_as_float(u);
}
__device__ __forceinline__ uint32_t smem_u32(const void* p) {
    uint32_t a;
    asm("{ .reg .u64 t; cvta.to.shared.u64 t, %1; cvt.u32.u64 %0, t; }" : "=r"(a) : "l"(p));
    return a;
}
__device__ __forceinline__ void cp_async16(uint32_t dst, const void* src) {
    asm volatile("cp.async.cg.shared.global [%0], [%1], 16;" :: "r"(dst), "l"(src) : "memory");
}
#define CP_COMMIT() asm volatile("cp.async.commit_group;" ::: "memory")
#define CP_WAIT(n)  asm volatile("cp.async.wait_group %0;" :: "n"(n) : "memory")

__device__ __forceinline__ void ldm_x4(uint32_t addr, uint32_t& r0, uint32_t& r1,
                                       uint32_t& r2, uint32_t& r3) {
    asm volatile("ldmatrix.sync.aligned.m8n8.x4.shared.b16 {%0,%1,%2,%3}, [%4];"
                 : "=r"(r0), "=r"(r1), "=r"(r2), "=r"(r3) : "r"(addr));
}
__device__ __forceinline__ void mma16816(float* c, const uint32_t* a,
                                         uint32_t b0, uint32_t b1) {
    asm volatile("mma.sync.aligned.m16n8k16.row.col.f32.bf16.bf16.f32 "
                 "{%0,%1,%2,%3}, {%4,%5,%6,%7}, {%8,%9}, {%0,%1,%2,%3};"
                 : "+f"(c[0]), "+f"(c[1]), "+f"(c[2]), "+f"(c[3])
                 : "r"(a[0]), "r"(a[1]), "r"(a[2]), "r"(a[3]), "r"(b0), "r"(b1));
}

// ---------------- smem layout (dynamic, per 64-row CTA) ----------------
#define XSTRIDE  260
#define SXF_BYTES (64*XSTRIDE*4)        // 66560
#define ASTRIDE  144
#define ACH_OFF  SXF_BYTES              // A bf16 chunk 64x144=9216 ; conv sIn / candList / sMn alias
#define ACH_BYTES (64*ASTRIDE)          // 9216
#define SMN_OFF  (ACH_OFF + 8192)       // sMn[4][64] floats = 1024 B at tail of ACH
#define B_OFF    (ACH_OFF + ACH_BYTES)  // 75776
#define BTILE    (256*ASTRIDE)          // 36864 (single buffer)
#define FUSED_SMEM (B_OFF + BTILE)      // 112640
#define CAND_CAP 2048                   // entries in ACH[0..8192)

// statics: sc2 2048 + sWred 32 + sKey 512 + s_idx 256 + s_red 256 + sCnt 4 + sIsLast 4 = 3112

// =====================================================================
// Kernel A: codebook -> bf16 + exact fp32 squared norms
// =====================================================================
__global__ __launch_bounds__(256) void prep_cbk_kernel(const float* __restrict__ cbk)
{
    __shared__ float red[256];
    const int k = blockIdx.x;
    const int t = threadIdx.x;
    float v = cbk[k * DMODEL + t];
    g_cbkb[k * DMODEL + t] = __float2bfloat16(v);
    red[t] = v * v;
    __syncthreads();
    for (int s = 128; s > 0; s >>= 1) {
        if (t < s) red[t] += red[t + s];
        __syncthreads();
    }
    if (t == 0) g_c2[k] = red[0];
}

// =====================================================================
// Kernel B: FUSED conv -> smem x-tile (64 rows) -> bf16 MMA VQ ->
//           warp-coop exact rescore -> quant write + loss. 2 CTAs/SM.
// grid 4096; 256 threads = 8 warps (2m x 4n)
// =====================================================================
__global__ __launch_bounds__(256, 2) void fused_kernel(
    const float* __restrict__ x, const float* __restrict__ cw,
    const float* __restrict__ cbias,
    const float* __restrict__ gam, const float* __restrict__ bet,
    const float* __restrict__ mu,  const float* __restrict__ var,
    const float* __restrict__ cbk, float* __restrict__ out)
{
    extern __shared__ __align__(16) char dsm[];
    __shared__ float sc2[KCODES];
    __shared__ float sWred[8];
    __shared__ unsigned long long sKey[64];
    __shared__ int   s_idx[64];
    __shared__ float s_red[64];
    __shared__ int   sCnt;
    __shared__ int   sIsLast;

    const int tid  = threadIdx.x;
    const int wid  = tid >> 5;       // 0..7
    const int lane = tid & 31;
    const int wm   = wid >> 2;       // 0..1  (32 rows each)
    const int wn   = wid & 3;        // 0..3  (64 codes within half)
    const int bx   = blockIdx.x;
    const int hw   = bx & 1;         // half-width (64 pooled cols)
    const int ph   = (bx >> 1) & 127;
    const int b    = bx >> 8;

    float* sXf = reinterpret_cast<float*>(dsm);
    float* sMn = reinterpret_cast<float*>(dsm + SMN_OFF);   // [4][64]
    const uint32_t smBase = smem_u32(dsm);

    sc2[tid] = g_c2[tid];
    sc2[tid + 256] = g_c2[tid + 256];
    if (tid < 64) sKey[tid] = 0xFFFFFFFFFFFFFFFFull;
    if (tid == 0) sCnt = 0;

    auto issue_B = [&](int p) {
        const int half = p >> 2;
        const int kc   = p & 3;
        const uint32_t buf = smBase + B_OFF;
#pragma unroll
        for (int it = 0; it < 8; it++) {
            int idx = tid + it * 256;
            int c   = idx >> 3;
            int g   = idx & 7;
            const void* src = g_cbkb + ((half * 256 + c) * DMODEL + kc * 64 + g * 8);
            cp_async16(buf + c * ASTRIDE + g * 16, src);
        }
        CP_COMMIT();
    };

    issue_B(0);   // overlaps conv phase (B buffer free during conv)

    // ================= conv phase (sliding-window, 64 pooled cols) =========
    {
        float (*sIn)[4][132] = reinterpret_cast<float (*)[4][132]>(dsm + ACH_OFF);
        const int d  = tid;
        const int h0 = 2 * ph - 1;
        const int c0 = hw * 128 - 1;            // global col of local col 0
        for (int t = tid; t < 3 * 4 * 132; t += 256) {
            int c   = t / 528;
            int rem = t - c * 528;
            int i   = rem / 132;
            int j   = rem - i * 132;
            int gr  = h0 + i;
            int gc  = c0 + j;
            float v = 0.f;
            if ((unsigned)gr < 256u && (unsigned)gc < 256u)
                v = x[(((b * 3 + c) << 8) + gr) * 256 + gc];
            sIn[c][i][j] = v;
        }

        unsigned long long w2[27];
#pragma unroll
        for (int j = 0; j < 27; j++) { float wv = cw[d * 27 + j]; w2[j] = pack2(wv, wv); }
        const float bias = cbias[d];
        const float inv  = gam[d] * rsqrtf(var[d] + BN_EPS);
        const float shf  = bet[d] - mu[d] * inv;

        __syncthreads();

        float2 cf[3][4];
        unsigned long long gp[3][4];
#pragma unroll
        for (int c = 0; c < 3; c++)
#pragma unroll
            for (int ro = 0; ro < 4; ro++) {
                cf[c][ro] = *reinterpret_cast<const float2*>(&sIn[c][ro][0]);
                gp[c][ro] = pack2(cf[c][ro].x, cf[c][ro].y);
            }

        float sumsq = 0.f;
#pragma unroll 2
        for (int pw = 0; pw < 64; ++pw) {
            unsigned long long acc0 = 0ull, acc1 = 0ull;
#pragma unroll
            for (int c = 0; c < 3; c++) {
                const int wb = c * 9;
#pragma unroll
                for (int ro = 0; ro < 4; ro++) {
                    float2 nx = *reinterpret_cast<const float2*>(&sIn[c][ro][2 * pw + 2]);
                    unsigned long long g01 = gp[c][ro];
                    unsigned long long g12 = pack2(cf[c][ro].y, nx.x);
                    unsigned long long g23 = pack2(nx.x, nx.y);
                    cf[c][ro] = nx;
                    gp[c][ro] = g23;
                    if (ro <= 2) {
                        fma2(acc0, g01, w2[wb + ro * 3 + 0]);
                        fma2(acc0, g12, w2[wb + ro * 3 + 1]);
                        fma2(acc0, g23, w2[wb + ro * 3 + 2]);
                    }
                    if (ro >= 1) {
                        fma2(acc1, g01, w2[wb + (ro - 1) * 3 + 0]);
                        fma2(acc1, g12, w2[wb + (ro - 1) * 3 + 1]);
                        fma2(acc1, g23, w2[wb + (ro - 1) * 3 + 2]);
                    }
                }
            }
            float a0, a1, b0v, b1v;
            unpack2(acc0, a0, a1);
            unpack2(acc1, b0v, b1v);
            float m = fmaxf(fmaxf(a0, a1), fmaxf(b0v, b1v)) + bias;
            float v = m * inv + shf;
            float g = 0.5f * v * (1.0f + erff(v * 0.7071067811865476f));
            sXf[pw * XSTRIDE + d] = g;
            sumsq += g * g;
        }

#pragma unroll
        for (int off = 16; off >= 1; off >>= 1)
            sumsq += __shfl_xor_sync(0xffffffffu, sumsq, off);
        if (lane == 0) sWred[wid] = sumsq;
        __syncthreads();
        if (tid == 0) {
            float s = 0.f;
#pragma unroll
            for (int i = 0; i < 8; i++) s += sWred[i];
            g_conv_partial[bx] = s;
        }
        __syncthreads();   // sXf complete; sIn region dead
    }

    // ================= VQ phase (8 phases, single-buffer B) =================
    uint32_t* candList = reinterpret_cast<uint32_t*>(dsm + ACH_OFF);
    float acc[2][8][4];   // [mt][jj][q] : 32 rows x 64 codes per warp

    for (int p = 0; p < 8; p++) {
        const int half = p >> 2;
        const int kc   = p & 3;
        const uint32_t bbuf = smBase + B_OFF;

        // B(p) already in flight (issued at end of previous phase or pre-conv)

        // ---- convert A chunk kc: sXf fp32 -> bf16 ldmatrix layout ----
        {
            const int r  = tid >> 2;          // 0..63
            const int kg = tid & 3;
            const float* src = sXf + r * XSTRIDE + kc * 64 + kg * 16;
            char* dstA = dsm + ACH_OFF + r * ASTRIDE + kg * 32;
#pragma unroll
            for (int i = 0; i < 4; i++) {
                float4 v = *reinterpret_cast<const float4*>(src + i * 4);
                __nv_bfloat162 h01 = __float22bfloat162_rn(make_float2(v.x, v.y));
                __nv_bfloat162 h23 = __float22bfloat162_rn(make_float2(v.z, v.w));
                uint2 st;
                st.x = *reinterpret_cast<uint32_t*>(&h01);
                st.y = *reinterpret_cast<uint32_t*>(&h23);
                *reinterpret_cast<uint2*>(dstA + i * 8) = st;
            }
        }

        CP_WAIT(0);
        __syncthreads();   // A chunk + B tile visible

        if (kc == 0) {
#pragma unroll
            for (int mt = 0; mt < 2; mt++)
#pragma unroll
                for (int j = 0; j < 8; j++)
#pragma unroll
                    for (int q = 0; q < 4; q++) acc[mt][j][q] = 0.f;
        }

#pragma unroll
        for (int ks = 0; ks < 4; ks++) {
            uint32_t a[2][4];
            const int grp = lane >> 3, rim = lane & 7;
#pragma unroll
            for (int mt = 0; mt < 2; mt++) {
                uint32_t row  = wm * 32 + mt * 16 + (grp & 1) * 8 + rim;
                uint32_t koff = ks * 32 + (grp >> 1) * 16;
                ldm_x4(smBase + ACH_OFF + row * ASTRIDE + koff,
                       a[mt][0], a[mt][1], a[mt][2], a[mt][3]);
            }
#pragma unroll
            for (int jjp = 0; jjp < 4; jjp++) {
                uint32_t codeInTile = wn * 64 + (2 * jjp + (grp >> 1)) * 8 + rim;
                uint32_t addr = bbuf + codeInTile * ASTRIDE + ks * 32 + (grp & 1) * 16;
                uint32_t b0, b1, b2, b3;
                ldm_x4(addr, b0, b1, b2, b3);
#pragma unroll
                for (int mt = 0; mt < 2; mt++) {
                    mma16816(acc[mt][2 * jjp],     a[mt], b0, b1);
                    mma16816(acc[mt][2 * jjp + 1], a[mt], b2, b3);
                }
            }
        }
        __syncthreads();   // A/B consumed

        if (p < 7) issue_B(p + 1);   // prefetch next tile into the (now free) buffer

        if (kc == 3) {
            // ---- epilogue: per-slot mins, single exchange, candidate push ----
            const int cbase = half * 256 + wn * 64 + (lane & 3) * 2;
#pragma unroll
            for (int slot = 0; slot < 4; slot++) {
                const int mt = slot >> 1;
                const int rh = slot & 1;
                float mn = __int_as_float(0x7f800000);
#pragma unroll
                for (int j = 0; j < 8; j++) {
#pragma unroll
                    for (int q = 0; q < 2; q++) {
                        float d = fmaf(-2.f, acc[mt][j][rh * 2 + q],
                                       sc2[cbase + j * 8 + q]);
                        mn = fminf(mn, d);
                    }
                }
                mn = fminf(mn, __shfl_xor_sync(0xffffffffu, mn, 1));
                mn = fminf(mn, __shfl_xor_sync(0xffffffffu, mn, 2));
                if ((lane & 3) == 0) {
                    const int rowLocal = wm * 32 + mt * 16 + rh * 8 + (lane >> 2);
                    sMn[wn * 64 + rowLocal] = mn;
                }
            }
            __syncthreads();

#pragma unroll
            for (int slot = 0; slot < 4; slot++) {
                const int mt = slot >> 1;
                const int rh = slot & 1;
                const int rowLocal = wm * 32 + mt * 16 + rh * 8 + (lane >> 2);
                const float thr = fminf(fminf(sMn[rowLocal], sMn[64 + rowLocal]),
                                        fminf(sMn[128 + rowLocal], sMn[192 + rowLocal]))
                                  + MARGIN;
#pragma unroll
                for (int u = 0; u < 16; u++) {
                    float d = fmaf(-2.f, acc[mt][u >> 1][rh * 2 + (u & 1)],
                                   sc2[cbase + (u >> 1) * 8 + (u & 1)]);
                    if (d < thr) {
                        int code = cbase + (u >> 1) * 8 + (u & 1);
                        int pos = atomicAdd(&sCnt, 1);
                        if (pos < CAND_CAP) {
                            candList[pos] = ((uint32_t)rowLocal << 16) | (uint32_t)code;
                        } else {
                            const float4* xr = reinterpret_cast<const float4*>(
                                sXf + rowLocal * XSTRIDE);
                            const float4* cr = reinterpret_cast<const float4*>(
                                cbk + (long long)code * DMODEL);
                            float s0 = 0.f, s1 = 0.f, s2 = 0.f, s3 = 0.f;
                            for (int t2 = 0; t2 < 64; t2++) {
                                float4 av = xr[t2];
                                float4 bv = cr[t2];
                                s0 = fmaf(av.x, bv.x, s0);
                                s1 = fmaf(av.y, bv.y, s1);
                                s2 = fmaf(av.z, bv.z, s2);
                                s3 = fmaf(av.w, bv.w, s3);
                            }
                            float de = fmaf(-2.f, (s0 + s1) + (s2 + s3), sc2[code]);
                            atomicMin(&sKey[rowLocal],
                                      ((unsigned long long)fenc(de) << 32) | (unsigned)code);
                        }
                    }
                }
            }

            // ---- warp-cooperative exact rescore of candidate list ----
            __syncthreads();
            const int total = min(sCnt, (int)CAND_CAP);
            for (int i = wid; i < total; i += 8) {
                uint32_t e = candList[i];
                int row  = (int)(e >> 16);
                int code = (int)(e & 0xffffu);
                const float4* xr = reinterpret_cast<const float4*>(sXf + row * XSTRIDE);
                const float4* cr = reinterpret_cast<const float4*>(
                    cbk + (long long)code * DMODEL);
                float4 a0 = xr[lane];
                float4 b0 = cr[lane];
                float4 a1 = xr[lane + 32];
                float4 b1 = cr[lane + 32];
                float s = a0.x * b0.x;
                s = fmaf(a0.y, b0.y, s);
                s = fmaf(a0.z, b0.z, s);
                s = fmaf(a0.w, b0.w, s);
                s = fmaf(a1.x, b1.x, s);
                s = fmaf(a1.y, b1.y, s);
                s = fmaf(a1.z, b1.z, s);
                s = fmaf(a1.w, b1.w, s);
#pragma unroll
                for (int off = 16; off >= 1; off >>= 1)
                    s += __shfl_xor_sync(0xffffffffu, s, off);
                if (lane == 0) {
                    float de = fmaf(-2.f, s, sc2[code]);
                    atomicMin(&sKey[row],
                              ((unsigned long long)fenc(de) << 32) | (unsigned)code);
                }
            }
            __syncthreads();
            if (tid == 0) sCnt = 0;
        }
    }

    // ---- final per-row results ----
    __syncthreads();
    if (tid < 64) {
        unsigned long long key = sKey[tid];
        int   c = (int)(unsigned)(key & 0xffffu);
        float e = fdec((unsigned)(key >> 32));
        s_idx[tid] = c;
        s_red[tid] = e;
        out[QUANT_ELEMS + ((long long)(b * 128 + ph) * 128) + hw * 64 + tid] = (float)c;
    }
    __syncthreads();

    for (int s = 32; s > 0; s >>= 1) {
        if (tid < s) s_red[tid] += s_red[tid + s];
        __syncthreads();
    }
    if (tid == 0) g_vq_partial[bx] = s_red[0];
    __syncthreads();   // all sXf reads done; dsm reusable

    // ================= quant write via smem staging =================
    {
        float* stage = reinterpret_cast<float*>(dsm);
#pragma unroll
        for (int i = 0; i < 8; i++) {
            int w = wid * 8 + i;
            int code = s_idx[w];
            const float4* crow = reinterpret_cast<const float4*>(
                cbk + (long long)code * DMODEL);
            float4 v0 = crow[lane];
            float4 v1 = crow[32 + lane];
            *reinterpret_cast<float4*>(stage + w * XSTRIDE + lane * 4)       = v0;
            *reinterpret_cast<float4*>(stage + w * XSTRIDE + 128 + lane * 4) = v1;
        }
        __syncthreads();

        const int w    = tid & 63;
        const int doff = tid >> 6;          // 0..3
        const long long outBase = ((long long)b * DMODEL * 128 + ph) * 128 + hw * 64 + w;
        for (int db = 0; db < DMODEL; db += 4) {
            int d = db + doff;
            float qv = stage[w * XSTRIDE + d];
            out[outBase + (long long)d * 16384] = qv;
        }
    }

    // ================= last-CTA loss reduction =================
    if (tid == 0) {
        __threadfence();
        unsigned ticket = atomicAdd(&g_done, 1u);
        sIsLast = (ticket == NCTA - 1u);
    }
    __syncthreads();
    if (sIsLast) {
        float s = 0.f;
        for (int i = tid; i < NCTA; i += 256)
            s += g_conv_partial[i] + g_vq_partial[i];
#pragma unroll
        for (int off = 16; off >= 1; off >>= 1)
            s += __shfl_xor_sync(0xffffffffu, s, off);
        if (lane == 0) sWred[wid] = s;
        __syncthreads();
        if (tid == 0) {
            float tot = 0.f;
#pragma unroll
            for (int i = 0; i < 8; i++) tot += sWred[i];
            out[QUANT_ELEMS + IDX_ELEMS] = tot * (1.0f / 67108864.0f);
        }
    }
}

// =====================================================================
extern "C" void kernel_launch(void* const* d_in, const int* in_sizes, int n_in,
                              void* d_out, int out_size)
{
    (void)in_sizes; (void)n_in; (void)out_size;
    const float* x    = (const float*)d_in[0];
    const float* cw   = (const float*)d_in[1];
    const float* cbia = (const float*)d_in[2];
    const float* gam  = (const float*)d_in[3];
    const float* bet  = (const float*)d_in[4];
    const float* mu   = (const float*)d_in[5];
    const float* var  = (const float*)d_in[6];
    const float* cbk  = (const float*)d_in[7];
    float* out = (float*)d_out;

    cudaFuncSetAttribute(fused_kernel, cudaFuncAttributeMaxDynamicSharedMemorySize,
                         FUSED_SMEM);

    void* donePtr = nullptr;
    cudaGetSymbolAddress(&donePtr, g_done);
    cudaMemsetAsync(donePtr, 0, sizeof(unsigned));

    prep_cbk_kernel<<<512, 256>>>(cbk);
    fused_kernel<<<NCTA, 256, FUSED_SMEM>>>(x, cw, cbia, gam, bet, mu, var, cbk, out);
}

// round 16
// speedup vs baseline: 1.4867x; 1.4867x over previous
#include <cuda_runtime.h>
#include <cuda_bf16.h>
#include <cstdint>

// ---------------- problem constants ----------------
#define BATCH   16
#define DMODEL  256
#define KCODES  512
#define HP      128
#define WP      128
#define NROWS   (BATCH*HP*WP)
#define QUANT_ELEMS ((long long)BATCH*DMODEL*HP*WP)   // 67108864
#define IDX_ELEMS   (BATCH*HP*WP)
#define BN_EPS 1e-5f
#define MARGIN 4.0f
#define NCTA 4096

// ---------------- scratch ----------------
__device__ __nv_bfloat16  g_cbkb[KCODES * DMODEL];
__device__ float g_c2[KCODES];
__device__ float g_conv_partial[NCTA];
__device__ float g_vq_partial[NCTA];
__device__ unsigned g_done;

// ---------------- helpers ----------------
__device__ __forceinline__ unsigned long long pack2(float a, float b) {
    unsigned long long r;
    asm("mov.b64 %0, {%1, %2};" : "=l"(r) : "f"(a), "f"(b));
    return r;
}
__device__ __forceinline__ void unpack2(unsigned long long v, float& a, float& b) {
    asm("mov.b64 {%0, %1}, %2;" : "=f"(a), "=f"(b) : "l"(v));
}
__device__ __forceinline__ void fma2(unsigned long long& acc,
                                     unsigned long long a, unsigned long long b) {
    asm("fma.rn.f32x2 %0, %1, %2, %3;" : "=l"(acc) : "l"(a), "l"(b), "l"(acc));
}
__device__ __forceinline__ unsigned fenc(float f) {
    unsigned u = __float_as_uint(f);
    return (u & 0x80000000u) ? ~u : (u | 0x80000000u);
}
__device__ __forceinline__ float fdec(unsigned e) {
    unsigned u = (e & 0x80000000u) ? (e ^ 0x80000000u) : ~e;
    return __uint_as_float(u);
}
__device__ __forceinline__ uint32_t smem_u32(const void* p) {
    uint32_t a;
    asm("{ .reg .u64 t; cvta.to.shared.u64 t, %1; cvt.u32.u64 %0, t; }" : "=r"(a) : "l"(p));
    return a;
}
__device__ __forceinline__ void cp_async16(uint32_t dst, const void* src) {
    asm volatile("cp.async.cg.shared.global [%0], [%1], 16;" :: "r"(dst), "l"(src) : "memory");
}
#define CP_COMMIT() asm volatile("cp.async.commit_group;" ::: "memory")
#define CP_WAIT(n)  asm volatile("cp.async.wait_group %0;" :: "n"(n) : "memory")

__device__ __forceinline__ void ldm_x4(uint32_t addr, uint32_t& r0, uint32_t& r1,
                                       uint32_t& r2, uint32_t& r3) {
    asm volatile("ldmatrix.sync.aligned.m8n8.x4.shared.b16 {%0,%1,%2,%3}, [%4];"
                 : "=r"(r0), "=r"(r1), "=r"(r2), "=r"(r3) : "r"(addr));
}
__device__ __forceinline__ void mma16816(float* c, const uint32_t* a,
                                         uint32_t b0, uint32_t b1) {
    asm volatile("mma.sync.aligned.m16n8k16.row.col.f32.bf16.bf16.f32 "
                 "{%0,%1,%2,%3}, {%4,%5,%6,%7}, {%8,%9}, {%0,%1,%2,%3};"
                 : "+f"(c[0]), "+f"(c[1]), "+f"(c[2]), "+f"(c[3])
                 : "r"(a[0]), "r"(a[1]), "r"(a[2]), "r"(a[3]), "r"(b0), "r"(b1));
}

// ---------------- smem layout (dynamic, per 64-row CTA) ----------------
#define XSTRIDE  260
#define SXF_BYTES (64*XSTRIDE*4)        // 66560
#define ASTRIDE  144
#define ACH_OFF  SXF_BYTES              // A bf16 chunk 64x144=9216 ; sIn / candList / sMn / s_idx alias
#define ACH_BYTES (64*ASTRIDE)          // 9216
#define SMN_OFF  (ACH_OFF + 8192)       // sMn[4][64] floats = 1024 B at tail of ACH
#define B_OFF    (ACH_OFF + ACH_BYTES)  // 75776
#define BTILE    (256*ASTRIDE)          // 36864 (single buffer)
#define FUSED_SMEM (B_OFF + BTILE)      // 112640
#define CAND_CAP 2048                   // entries in ACH[0..8192)

// statics: sc2 2048 + sWred 32 + sKey 512 + sCnt 4 + sIsLast 4 = 2600 B
// per-CTA smem: 112640 + 2600 = 115240 -> 115712 (1KB gran) + 1024 reserve = 116736
// 2 CTAs/SM: 233472 == per-SM limit -> fits.

// =====================================================================
// Kernel A: codebook -> bf16 + exact fp32 squared norms
// =====================================================================
__global__ __launch_bounds__(256) void prep_cbk_kernel(const float* __restrict__ cbk)
{
    __shared__ float red[256];
    const int k = blockIdx.x;
    const int t = threadIdx.x;
    float v = cbk[k * DMODEL + t];
    g_cbkb[k * DMODEL + t] = __float2bfloat16(v);
    red[t] = v * v;
    __syncthreads();
    for (int s = 128; s > 0; s >>= 1) {
        if (t < s) red[t] += red[t + s];
        __syncthreads();
    }
    if (t == 0) g_c2[k] = red[0];
}

// =====================================================================
// Kernel B: FUSED conv -> smem x-tile (64 rows) -> bf16 MMA VQ ->
//           warp-coop exact rescore -> quant write + loss. 2 CTAs/SM.
// grid 4096; 256 threads = 8 warps (2m x 4n)
// =====================================================================
__global__ __launch_bounds__(256, 2) void fused_kernel(
    const float* __restrict__ x, const float* __restrict__ cw,
    const float* __restrict__ cbias,
    const float* __restrict__ gam, const float* __restrict__ bet,
    const float* __restrict__ mu,  const float* __restrict__ var,
    const float* __restrict__ cbk, float* __restrict__ out)
{
    extern __shared__ __align__(16) char dsm[];
    __shared__ float sc2[KCODES];
    __shared__ float sWred[8];
    __shared__ unsigned long long sKey[64];
    __shared__ int   sCnt;
    __shared__ int   sIsLast;

    const int tid  = threadIdx.x;
    const int wid  = tid >> 5;       // 0..7
    const int lane = tid & 31;
    const int wm   = wid >> 2;       // 0..1  (32 rows each)
    const int wn   = wid & 3;        // 0..3  (64 codes within half)
    const int bx   = blockIdx.x;
    const int hw   = bx & 1;         // half-width (64 pooled cols)
    const int ph   = (bx >> 1) & 127;
    const int b    = bx >> 8;

    float* sXf = reinterpret_cast<float*>(dsm);
    float* sMn = reinterpret_cast<float*>(dsm + SMN_OFF);          // [4][64], VQ only
    int*   s_idx = reinterpret_cast<int*>(dsm + SMN_OFF);          // post-VQ alias
    float* s_red = reinterpret_cast<float*>(dsm + SMN_OFF + 256);  // post-VQ alias
    const uint32_t smBase = smem_u32(dsm);

    sc2[tid] = g_c2[tid];
    sc2[tid + 256] = g_c2[tid + 256];
    if (tid < 64) sKey[tid] = 0xFFFFFFFFFFFFFFFFull;
    if (tid == 0) sCnt = 0;

    auto issue_B = [&](int p) {
        const int half = p >> 2;
        const int kc   = p & 3;
        const uint32_t buf = smBase + B_OFF;
#pragma unroll
        for (int it = 0; it < 8; it++) {
            int idx = tid + it * 256;
            int c   = idx >> 3;
            int g   = idx & 7;
            const void* src = g_cbkb + ((half * 256 + c) * DMODEL + kc * 64 + g * 8);
            cp_async16(buf + c * ASTRIDE + g * 16, src);
        }
        CP_COMMIT();
    };

    issue_B(0);   // overlaps conv phase (B buffer free during conv)

    // ================= conv phase (sliding-window, 64 pooled cols) =========
    {
        float (*sIn)[4][132] = reinterpret_cast<float (*)[4][132]>(dsm + ACH_OFF);
        const int d  = tid;
        const int h0 = 2 * ph - 1;
        const int c0 = hw * 128 - 1;            // global col of local col 0
        for (int t = tid; t < 3 * 4 * 132; t += 256) {
            int c   = t / 528;
            int rem = t - c * 528;
            int i   = rem / 132;
            int j   = rem - i * 132;
            int gr  = h0 + i;
            int gc  = c0 + j;
            float v = 0.f;
            if ((unsigned)gr < 256u && (unsigned)gc < 256u)
                v = x[(((b * 3 + c) << 8) + gr) * 256 + gc];
            sIn[c][i][j] = v;
        }

        unsigned long long w2[27];
#pragma unroll
        for (int j = 0; j < 27; j++) { float wv = cw[d * 27 + j]; w2[j] = pack2(wv, wv); }
        const float bias = cbias[d];
        const float inv  = gam[d] * rsqrtf(var[d] + BN_EPS);
        const float shf  = bet[d] - mu[d] * inv;

        __syncthreads();

        float2 cf[3][4];
        unsigned long long gp[3][4];
#pragma unroll
        for (int c = 0; c < 3; c++)
#pragma unroll
            for (int ro = 0; ro < 4; ro++) {
                cf[c][ro] = *reinterpret_cast<const float2*>(&sIn[c][ro][0]);
                gp[c][ro] = pack2(cf[c][ro].x, cf[c][ro].y);
            }

        float sumsq = 0.f;
#pragma unroll 2
        for (int pw = 0; pw < 64; ++pw) {
            unsigned long long acc0 = 0ull, acc1 = 0ull;
#pragma unroll
            for (int c = 0; c < 3; c++) {
                const int wb = c * 9;
#pragma unroll
                for (int ro = 0; ro < 4; ro++) {
                    float2 nx = *reinterpret_cast<const float2*>(&sIn[c][ro][2 * pw + 2]);
                    unsigned long long g01 = gp[c][ro];
                    unsigned long long g12 = pack2(cf[c][ro].y, nx.x);
                    unsigned long long g23 = pack2(nx.x, nx.y);
                    cf[c][ro] = nx;
                    gp[c][ro] = g23;
                    if (ro <= 2) {
                        fma2(acc0, g01, w2[wb + ro * 3 + 0]);
                        fma2(acc0, g12, w2[wb + ro * 3 + 1]);
                        fma2(acc0, g23, w2[wb + ro * 3 + 2]);
                    }
                    if (ro >= 1) {
                        fma2(acc1, g01, w2[wb + (ro - 1) * 3 + 0]);
                        fma2(acc1, g12, w2[wb + (ro - 1) * 3 + 1]);
                        fma2(acc1, g23, w2[wb + (ro - 1) * 3 + 2]);
                    }
                }
            }
            float a0, a1, b0v, b1v;
            unpack2(acc0, a0, a1);
            unpack2(acc1, b0v, b1v);
            float m = fmaxf(fmaxf(a0, a1), fmaxf(b0v, b1v)) + bias;
            float v = m * inv + shf;
            float g = 0.5f * v * (1.0f + erff(v * 0.7071067811865476f));
            sXf[pw * XSTRIDE + d] = g;
            sumsq += g * g;
        }

#pragma unroll
        for (int off = 16; off >= 1; off >>= 1)
            sumsq += __shfl_xor_sync(0xffffffffu, sumsq, off);
        if (lane == 0) sWred[wid] = sumsq;
        __syncthreads();
        if (tid == 0) {
            float s = 0.f;
#pragma unroll
            for (int i = 0; i < 8; i++) s += sWred[i];
            g_conv_partial[bx] = s;
        }
        __syncthreads();   // sXf complete; sIn region dead
    }

    // ================= VQ phase (8 phases, single-buffer B) =================
    uint32_t* candList = reinterpret_cast<uint32_t*>(dsm + ACH_OFF);
    float acc[2][8][4];   // [mt][jj][q] : 32 rows x 64 codes per warp

    for (int p = 0; p < 8; p++) {
        const int half = p >> 2;
        const int kc   = p & 3;
        const uint32_t bbuf = smBase + B_OFF;

        // ---- convert A chunk kc: sXf fp32 -> bf16 ldmatrix layout ----
        {
            const int r  = tid >> 2;          // 0..63
            const int kg = tid & 3;
            const float* src = sXf + r * XSTRIDE + kc * 64 + kg * 16;
            char* dstA = dsm + ACH_OFF + r * ASTRIDE + kg * 32;
#pragma unroll
            for (int i = 0; i < 4; i++) {
                float4 v = *reinterpret_cast<const float4*>(src + i * 4);
                __nv_bfloat162 h01 = __float22bfloat162_rn(make_float2(v.x, v.y));
                __nv_bfloat162 h23 = __float22bfloat162_rn(make_float2(v.z, v.w));
                uint2 st;
                st.x = *reinterpret_cast<uint32_t*>(&h01);
                st.y = *reinterpret_cast<uint32_t*>(&h23);
                *reinterpret_cast<uint2*>(dstA + i * 8) = st;
            }
        }

        CP_WAIT(0);
        __syncthreads();   // A chunk + B tile visible

        if (kc == 0) {
#pragma unroll
            for (int mt = 0; mt < 2; mt++)
#pragma unroll
                for (int j = 0; j < 8; j++)
#pragma unroll
                    for (int q = 0; q < 4; q++) acc[mt][j][q] = 0.f;
        }

#pragma unroll
        for (int ks = 0; ks < 4; ks++) {
            uint32_t a[2][4];
            const int grp = lane >> 3, rim = lane & 7;
#pragma unroll
            for (int mt = 0; mt < 2; mt++) {
                uint32_t row  = wm * 32 + mt * 16 + (grp & 1) * 8 + rim;
                uint32_t koff = ks * 32 + (grp >> 1) * 16;
                ldm_x4(smBase + ACH_OFF + row * ASTRIDE + koff,
                       a[mt][0], a[mt][1], a[mt][2], a[mt][3]);
            }
#pragma unroll
            for (int jjp = 0; jjp < 4; jjp++) {
                uint32_t codeInTile = wn * 64 + (2 * jjp + (grp >> 1)) * 8 + rim;
                uint32_t addr = bbuf + codeInTile * ASTRIDE + ks * 32 + (grp & 1) * 16;
                uint32_t b0, b1, b2, b3;
                ldm_x4(addr, b0, b1, b2, b3);
#pragma unroll
                for (int mt = 0; mt < 2; mt++) {
                    mma16816(acc[mt][2 * jjp],     a[mt], b0, b1);
                    mma16816(acc[mt][2 * jjp + 1], a[mt], b2, b3);
                }
            }
        }
        __syncthreads();   // A/B consumed

        if (p < 7) issue_B(p + 1);   // prefetch next tile into the (now free) buffer

        if (kc == 3) {
            // ---- epilogue: per-slot mins, single exchange, candidate push ----
            const int cbase = half * 256 + wn * 64 + (lane & 3) * 2;
#pragma unroll
            for (int slot = 0; slot < 4; slot++) {
                const int mt = slot >> 1;
                const int rh = slot & 1;
                float mn = __int_as_float(0x7f800000);
#pragma unroll
                for (int j = 0; j < 8; j++) {
#pragma unroll
                    for (int q = 0; q < 2; q++) {
                        float d = fmaf(-2.f, acc[mt][j][rh * 2 + q],
                                       sc2[cbase + j * 8 + q]);
                        mn = fminf(mn, d);
                    }
                }
                mn = fminf(mn, __shfl_xor_sync(0xffffffffu, mn, 1));
                mn = fminf(mn, __shfl_xor_sync(0xffffffffu, mn, 2));
                if ((lane & 3) == 0) {
                    const int rowLocal = wm * 32 + mt * 16 + rh * 8 + (lane >> 2);
                    sMn[wn * 64 + rowLocal] = mn;
                }
            }
            __syncthreads();

#pragma unroll
            for (int slot = 0; slot < 4; slot++) {
                const int mt = slot >> 1;
                const int rh = slot & 1;
                const int rowLocal = wm * 32 + mt * 16 + rh * 8 + (lane >> 2);
                const float thr = fminf(fminf(sMn[rowLocal], sMn[64 + rowLocal]),
                                        fminf(sMn[128 + rowLocal], sMn[192 + rowLocal]))
                                  + MARGIN;
#pragma unroll
                for (int u = 0; u < 16; u++) {
                    float d = fmaf(-2.f, acc[mt][u >> 1][rh * 2 + (u & 1)],
                                   sc2[cbase + (u >> 1) * 8 + (u & 1)]);
                    if (d < thr) {
                        int code = cbase + (u >> 1) * 8 + (u & 1);
                        int pos = atomicAdd(&sCnt, 1);
                        if (pos < CAND_CAP) {
                            candList[pos] = ((uint32_t)rowLocal << 16) | (uint32_t)code;
                        } else {
                            const float4* xr = reinterpret_cast<const float4*>(
                                sXf + rowLocal * XSTRIDE);
                            const float4* cr = reinterpret_cast<const float4*>(
                                cbk + (long long)code * DMODEL);
                            float s0 = 0.f, s1 = 0.f, s2 = 0.f, s3 = 0.f;
                            for (int t2 = 0; t2 < 64; t2++) {
                                float4 av = xr[t2];
                                float4 bv = cr[t2];
                                s0 = fmaf(av.x, bv.x, s0);
                                s1 = fmaf(av.y, bv.y, s1);
                                s2 = fmaf(av.z, bv.z, s2);
                                s3 = fmaf(av.w, bv.w, s3);
                            }
                            float de = fmaf(-2.f, (s0 + s1) + (s2 + s3), sc2[code]);
                            atomicMin(&sKey[rowLocal],
                                      ((unsigned long long)fenc(de) << 32) | (unsigned)code);
                        }
                    }
                }
            }

            // ---- warp-cooperative exact rescore of candidate list ----
            __syncthreads();
            const int total = min(sCnt, (int)CAND_CAP);
            for (int i = wid; i < total; i += 8) {
                uint32_t e = candList[i];
                int row  = (int)(e >> 16);
                int code = (int)(e & 0xffffu);
                const float4* xr = reinterpret_cast<const float4*>(sXf + row * XSTRIDE);
                const float4* cr = reinterpret_cast<const float4*>(
                    cbk + (long long)code * DMODEL);
                float4 a0 = xr[lane];
                float4 b0 = cr[lane];
                float4 a1 = xr[lane + 32];
                float4 b1 = cr[lane + 32];
                float s = a0.x * b0.x;
                s = fmaf(a0.y, b0.y, s);
                s = fmaf(a0.z, b0.z, s);
                s = fmaf(a0.w, b0.w, s);
                s = fmaf(a1.x, b1.x, s);
                s = fmaf(a1.y, b1.y, s);
                s = fmaf(a1.z, b1.z, s);
                s = fmaf(a1.w, b1.w, s);
#pragma unroll
                for (int off = 16; off >= 1; off >>= 1)
                    s += __shfl_xor_sync(0xffffffffu, s, off);
                if (lane == 0) {
                    float de = fmaf(-2.f, s, sc2[code]);
                    atomicMin(&sKey[row],
                              ((unsigned long long)fenc(de) << 32) | (unsigned)code);
                }
            }
            __syncthreads();
            if (tid == 0) sCnt = 0;
        }
    }

    // ---- final per-row results (sMn dead; s_idx/s_red alias its space) ----
    __syncthreads();
    if (tid < 64) {
        unsigned long long key = sKey[tid];
        int   c = (int)(unsigned)(key & 0xffffu);
        float e = fdec((unsigned)(key >> 32));
        s_idx[tid] = c;
        s_red[tid] = e;
        out[QUANT_ELEMS + ((long long)(b * 128 + ph) * 128) + hw * 64 + tid] = (float)c;
    }
    __syncthreads();

    for (int s = 32; s > 0; s >>= 1) {
        if (tid < s) s_red[tid] += s_red[tid + s];
        __syncthreads();
    }
    if (tid == 0) g_vq_partial[bx] = s_red[0];
    __syncthreads();   // all sXf reads done; sXf region reusable (s_idx survives in ACH tail)

    // ================= quant write via smem staging =================
    {
        float* stage = reinterpret_cast<float*>(dsm);
#pragma unroll
        for (int i = 0; i < 8; i++) {
            int w = wid * 8 + i;
            int code = s_idx[w];
            const float4* crow = reinterpret_cast<const float4*>(
                cbk + (long long)code * DMODEL);
            float4 v0 = crow[lane];
            float4 v1 = crow[32 + lane];
            *reinterpret_cast<float4*>(stage + w * XSTRIDE + lane * 4)       = v0;
            *reinterpret_cast<float4*>(stage + w * XSTRIDE + 128 + lane * 4) = v1;
        }
        __syncthreads();

        const int w    = tid & 63;
        const int doff = tid >> 6;          // 0..3
        const long long outBase = ((long long)b * DMODEL * 128 + ph) * 128 + hw * 64 + w;
        for (int db = 0; db < DMODEL; db += 4) {
            int d = db + doff;
            float qv = stage[w * XSTRIDE + d];
            out[outBase + (long long)d * 16384] = qv;
        }
    }

    // ================= last-CTA loss reduction =================
    if (tid == 0) {
        __threadfence();
        unsigned ticket = atomicAdd(&g_done, 1u);
        sIsLast = (ticket == NCTA - 1u);
    }
    __syncthreads();
    if (sIsLast) {
        float s = 0.f;
        for (int i = tid; i < NCTA; i += 256)
            s += g_conv_partial[i] + g_vq_partial[i];
#pragma unroll
        for (int off = 16; off >= 1; off >>= 1)
            s += __shfl_xor_sync(0xffffffffu, s, off);
        if (lane == 0) sWred[wid] = s;
        __syncthreads();
        if (tid == 0) {
            float tot = 0.f;
#pragma unroll
            for (int i = 0; i < 8; i++) tot += sWred[i];
            out[QUANT_ELEMS + IDX_ELEMS] = tot * (1.0f / 67108864.0f);
        }
    }
}

// =====================================================================
extern "C" void kernel_launch(void* const* d_in, const int* in_sizes, int n_in,
                              void* d_out, int out_size)
{
    (void)in_sizes; (void)n_in; (void)out_size;
    const float* x    = (const float*)d_in[0];
    const float* cw   = (const float*)d_in[1];
    const float* cbia = (const float*)d_in[2];
    const float* gam  = (const float*)d_in[3];
    const float* bet  = (const float*)d_in[4];
    const float* mu   = (const float*)d_in[5];
    const float* var  = (const float*)d_in[6];
    const float* cbk  = (const float*)d_in[7];
    float* out = (float*)d_out;

    cudaFuncSetAttribute(fused_kernel, cudaFuncAttributeMaxDynamicSharedMemorySize,
                         FUSED_SMEM);

    void* donePtr = nullptr;
    cudaGetSymbolAddress(&donePtr, g_done);
    cudaMemsetAsync(donePtr, 0, sizeof(unsigned));

    prep_cbk_kernel<<<512, 256>>>(cbk);
    fused_kernel<<<NCTA, 256, FUSED_SMEM>>>(x, cw, cbia, gam, bet, mu, var, cbk, out);
}